// round 9
// baseline (speedup 1.0000x reference)
#include <cuda_runtime.h>
#include <cstdint>

#define H 2048
#define B 16
#define S 256
#define V 32000
#define NBLK 128
#define NTHR 512

typedef unsigned long long ull;

__device__ float g_gamma_exp[H];
__device__ float g_E[2][H * B];        // exp(y_t - m_{t-1}), double buffered by t&1
__device__ float g_part[2][NBLK * B];  // per-block per-b row maxes of y_t
__device__ unsigned g_flag[NBLK];      // block published step t => flag == t+1

__device__ __forceinline__ ull splat2(float v) {
    ull r; asm("mov.b64 %0, {%1, %1};" : "=l"(r) : "f"(v)); return r;
}
__device__ __forceinline__ ull fma2(ull a, ull b, ull c) {
    ull d; asm("fma.rn.f32x2 %0, %1, %2, %3;" : "=l"(d) : "l"(a), "l"(b), "l"(c)); return d;
}
__device__ __forceinline__ ull add2(ull a, ull b) {
    ull d; asm("add.rn.f32x2 %0, %1, %2;" : "=l"(d) : "l"(a), "l"(b)); return d;
}
__device__ __forceinline__ void upk(ull v, float& lo, float& hi) {
    asm("mov.b64 {%0, %1}, %2;" : "=f"(lo), "=f"(hi) : "l"(v));
}
__device__ __forceinline__ ull shflx16(ull v) {
    unsigned lo = (unsigned)v, hi = (unsigned)(v >> 32);
    lo = __shfl_xor_sync(0xffffffffu, lo, 16);
    hi = __shfl_xor_sync(0xffffffffu, hi, 16);
    return ((ull)hi << 32) | lo;
}
__device__ __forceinline__ unsigned ld_acq(const unsigned* p) {
    unsigned v;
    asm volatile("ld.acquire.gpu.global.u32 %0, [%1];" : "=r"(v) : "l"(p) : "memory");
    return v;
}
__device__ __forceinline__ void st_rel(unsigned* p, unsigned v) {
    asm volatile("st.release.gpu.global.u32 [%0], %1;" :: "l"(p), "r"(v) : "memory");
}

// ---------------------------------------------------------------------------
__global__ void init_flags_kernel() {
    if (threadIdx.x < NBLK) g_flag[threadIdx.x] = 0u;
}

// ---------------------------------------------------------------------------
__global__ void gamma_kernel(const float* __restrict__ gamma) {
    __shared__ float red[256];
    __shared__ float s_max, s_sum;
    int tid = threadIdx.x;
    float mx = -3.4e38f;
    for (int i = tid; i < H; i += 256) mx = fmaxf(mx, gamma[i]);
    red[tid] = mx;
    __syncthreads();
    for (int o = 128; o > 0; o >>= 1) {
        if (tid < o) red[tid] = fmaxf(red[tid], red[tid + o]);
        __syncthreads();
    }
    if (tid == 0) s_max = red[0];
    __syncthreads();
    float m = s_max;
    float sm = 0.f;
    for (int i = tid; i < H; i += 256) sm += __expf(gamma[i] - m);
    __syncthreads();
    red[tid] = sm;
    __syncthreads();
    for (int o = 128; o > 0; o >>= 1) {
        if (tid < o) red[tid] += red[tid + o];
        __syncthreads();
    }
    if (tid == 0) s_sum = red[0];
    __syncthreads();
    float inv = 1.0f / s_sum;
    for (int i = tid; i < H; i += 256) g_gamma_exp[i] = __expf(gamma[i] - m) * inv;
}

// ---------------------------------------------------------------------------
// persistent kernel: t=0 init + 255 steps + final fold (blocks 0..15)
// ---------------------------------------------------------------------------
__global__ void __launch_bounds__(NTHR, 1) hmm_persist(
    const int* __restrict__ ids, const float* __restrict__ alpha,
    const float* __restrict__ beta, float* __restrict__ out) {
    extern __shared__ float smem[];
    float* s_a = smem;               // [2048][16] alpha slice [k][r] (131072B)
    float* s_part = s_a + H * 16;    // [16 row][16 b][16 warp] partials (16KB)
    float* s_y = s_part + 256 * 16;  // [256]
    float* s_red = s_y + 256;        // [16 warp][16 b] m-reduce stage

    const int tid = threadIdx.x;
    const int blk = blockIdx.x;
    const int r0 = blk * 16;
    const int lane = tid & 31, w = tid >> 5;
    const int bg = lane & 3;                   // b group: b = bg*4..bg*4+3
    const int rg = (lane >> 2) & 3;            // row group: rows rg*4..rg*4+3
    const int khalf = lane >> 4;               // k parity in warp's 128-k slice
    const int orow = tid >> 4, ob = tid & 15;  // epilogue mapping (tid<256)
    const bool epi = (tid < 256);

    // stage alpha slice transposed: s_a[k*16 + rl] = alpha[(r0+rl)*H + k]
    for (int rl = 0; rl < 16; rl++) {
        const float* ap = alpha + (size_t)(r0 + rl) * H;
        for (int k = tid; k < H; k += NTHR) s_a[k * 16 + rl] = __ldg(ap + k);
    }
    __syncthreads();

    float m_prev = 0.f;  // shift used when publishing E_{t-1} (uniform across blocks)

    // ---- t = 0: y0 = masked beta gather; E_0 = exp(y0) (y0 <= 0, shift 0)
    {
        float y0 = 0.f;
        if (epi) {
            int id = __ldg(&ids[ob * S + (S - 1)]);
            float bv = __ldg(&beta[(size_t)(r0 + orow) * V + (id < 0 ? 0 : id)]);
            y0 = (id < 0) ? 0.f : bv;
            s_y[tid] = y0;
            g_E[0][(r0 + orow) * B + ob] = __expf(y0);
        }
        __syncthreads();
        if (tid < 16) {
            float mx = s_y[tid];
            #pragma unroll
            for (int rr = 1; rr < 16; rr++) mx = fmaxf(mx, s_y[rr * 16 + tid]);
            g_part[0][blk * B + tid] = mx;
        }
        __syncthreads();
        if (tid == 0) st_rel(&g_flag[blk], 1u);
        if (epi) out[(size_t)(r0 + orow) * B + ob] = y0;
    }

    // ---- main recurrence
    for (int t = 1; t < S; t++) {
        const int par = (t - 1) & 1;

        // prefetch ip (independent of any flag)
        float ipv = 0.f;
        if (epi) {
            int id = __ldg(&ids[ob * S + (S - 1 - t)]);
            float bv = __ldg(&beta[(size_t)(r0 + orow) * V + (id < 0 ? 0 : id)]);
            ipv = (id < 0) ? 0.f : bv;
        }

        // per-warp wait: this warp's 8 producer blocks (k-rows 128w..128w+127)
        if (lane < 8) {
            const unsigned* fp = &g_flag[w * 8 + lane];
            if (ld_acq(fp) < (unsigned)t) {
                do { __nanosleep(32); } while (ld_acq(fp) < (unsigned)t);
            }
        }
        __syncwarp();

        // prefetch m-parts of THIS WARP'S waited producer blocks (8w..8w+7);
        // lane < 16 handles batch b = lane.  Reduced after the dot.
        float mp[8];
        if (lane < 16) {
            const float* gp = g_part[par];
            #pragma unroll
            for (int j = 0; j < 8; j++)
                mp[j] = __ldcg(gp + (w * 8 + j) * B + lane);
        }

        // ---- dot: acc[rowlane][bpair] over this warp's 128 k (64 per khalf)
        const float* Eg = g_E[par];
        ull acc[4][2];
        #pragma unroll
        for (int l = 0; l < 4; l++) { acc[l][0] = 0ull; acc[l][1] = 0ull; }

        const int kbase = w * 128 + khalf;
        #pragma unroll 8
        for (int i = 0; i < 64; i++) {
            const int k = kbase + 2 * i;
            ulonglong2 ev = __ldcg(reinterpret_cast<const ulonglong2*>(Eg + k * B + bg * 4));
            float4 av = *reinterpret_cast<const float4*>(s_a + k * 16 + rg * 4);
            const ull a0 = splat2(av.x), a1 = splat2(av.y);
            const ull a2 = splat2(av.z), a3 = splat2(av.w);
            acc[0][0] = fma2(a0, ev.x, acc[0][0]);
            acc[0][1] = fma2(a0, ev.y, acc[0][1]);
            acc[1][0] = fma2(a1, ev.x, acc[1][0]);
            acc[1][1] = fma2(a1, ev.y, acc[1][1]);
            acc[2][0] = fma2(a2, ev.x, acc[2][0]);
            acc[2][1] = fma2(a2, ev.y, acc[2][1]);
            acc[3][0] = fma2(a3, ev.x, acc[3][0]);
            acc[3][1] = fma2(a3, ev.y, acc[3][1]);
        }

        // m-part reduce of this warp's producers into smem
        if (lane < 16) {
            float mx = mp[0];
            #pragma unroll
            for (int j = 1; j < 8; j++) mx = fmaxf(mx, mp[j]);
            s_red[w * 16 + lane] = mx;
        }

        // combine khalf halves, store partials
        #pragma unroll
        for (int l = 0; l < 4; l++) {
            acc[l][0] = add2(acc[l][0], shflx16(acc[l][0]));
            acc[l][1] = add2(acc[l][1], shflx16(acc[l][1]));
        }
        if (khalf == 0) {
            #pragma unroll
            for (int l = 0; l < 4; l++) {
                float f0, f1;
                upk(acc[l][0], f0, f1);
                s_part[((rg * 4 + l) * 16 + bg * 4 + 0) * 16 + w] = f0;
                s_part[((rg * 4 + l) * 16 + bg * 4 + 1) * 16 + w] = f1;
                upk(acc[l][1], f0, f1);
                s_part[((rg * 4 + l) * 16 + bg * 4 + 2) * 16 + w] = f0;
                s_part[((rg * 4 + l) * 16 + bg * 4 + 3) * 16 + w] = f1;
            }
        }
        __syncthreads();

        // epilogue: y = log(sum) + m_{t-2} + ip;  E_t = exp(y - m_{t-1})
        float y = 0.f, Mb = 0.f;
        if (epi) {
            Mb = s_red[ob];
            #pragma unroll
            for (int c = 1; c < 16; c++) Mb = fmaxf(Mb, s_red[c * 16 + ob]);
            const float* pp = s_part + tid * 16;
            float sum = 0.f;
            #pragma unroll
            for (int c = 0; c < 16; c++) sum += pp[c];
            y = __logf(sum) + m_prev + ipv;
            s_y[tid] = y;
            g_E[t & 1][(r0 + orow) * B + ob] = __expf(y - Mb);
            m_prev = Mb;  // next step's reconstruction shift (uniform across blocks)
        }
        __syncthreads();
        if (tid < 16) {
            float mx = s_y[tid];
            #pragma unroll
            for (int rr = 1; rr < 16; rr++) mx = fmaxf(mx, s_y[rr * 16 + tid]);
            g_part[t & 1][blk * B + tid] = mx;
        }
        __syncthreads();
        if (tid == 0) st_rel(&g_flag[blk], (unsigned)(t + 1));

        // ys store off the critical path
        if (epi) out[(size_t)t * H * B + (size_t)(r0 + orow) * B + ob] = y;
    }

    // ---- final fold: block b (<16) computes final[b] from E_{S-1} directly.
    //      E_{S-1} = exp(y_{S-1} - m_{S-2})  (shift = global max of y_{S-2}!)
    //      final[b] = log( sum_h gamma_exp[h] * E[h,b] ) + m_{S-2,b}
    if (blk < 16) {
        if (tid < NBLK) {
            const unsigned* fp = &g_flag[tid];
            if (ld_acq(fp) < (unsigned)S) {
                do { __nanosleep(32); } while (ld_acq(fp) < (unsigned)S);
            }
        }
        __syncthreads();
        const float* El = g_E[(S - 1) & 1];
        float sm = 0.f;
        #pragma unroll
        for (int i = 0; i < 4; i++) {
            int h = tid + i * NTHR;
            sm += g_gamma_exp[h] * __ldcg(El + (size_t)h * B + blk);
        }
        #pragma unroll
        for (int o = 16; o > 0; o >>= 1) sm += __shfl_xor_sync(0xffffffffu, sm, o);
        if (lane == 0) s_red[w] = sm;
        // m_{S-2, b}: max over the 128 blocks' row maxes of y_{S-2}
        // (buffer (S-2)&1, written at step S-2, untouched afterwards)
        float mx = -3.4e38f;
        if (tid < NBLK) mx = __ldcg(g_part[(S - 2) & 1] + tid * B + blk);
        #pragma unroll
        for (int o = 16; o > 0; o >>= 1)
            mx = fmaxf(mx, __shfl_xor_sync(0xffffffffu, mx, o));
        if (lane == 0) s_y[w] = mx;
        __syncthreads();
        if (tid == 0) {
            float tot = 0.f;
            #pragma unroll
            for (int c = 0; c < 16; c++) tot += s_red[c];
            float M = fmaxf(s_y[0], fmaxf(s_y[1], fmaxf(s_y[2], s_y[3])));
            out[(size_t)S * H * B + blk] = __logf(tot) + M;
        }
    }
}

// ---------------------------------------------------------------------------
extern "C" void kernel_launch(void* const* d_in, const int* in_sizes, int n_in,
                              void* d_out, int out_size) {
    const int* ids = (const int*)d_in[0];        // (B, S) int32
    const float* alpha = (const float*)d_in[1];  // (H, H)
    const float* beta = (const float*)d_in[2];   // (H, V)
    const float* gamma = (const float*)d_in[3];  // (H,)
    float* out = (float*)d_out;                  // ys (S,H,B) then final (B,)

    const int smem_main = (H * 16 + 256 * 16 + 256 + 256) * (int)sizeof(float);
    cudaFuncSetAttribute(hmm_persist, cudaFuncAttributeMaxDynamicSharedMemorySize,
                         smem_main);

    init_flags_kernel<<<1, 128>>>();
    gamma_kernel<<<1, 256>>>(gamma);
    hmm_persist<<<NBLK, NTHR, smem_main>>>(ids, alpha, beta, out);
}

// round 10
// speedup vs baseline: 1.5839x; 1.5839x over previous
#include <cuda_runtime.h>
#include <cstdint>

#define H 2048
#define B 16
#define S 256
#define V 32000
#define NBLK 128
#define NTHR 512

typedef unsigned long long ull;

__device__ float g_E[2][H * B];        // exp(y_t - shift), double buffered by t&1
__device__ float g_part[2][NBLK * B];  // per-block per-b row maxes of y_t
__device__ unsigned g_flag[NBLK];      // monotonic: block done step t of epoch => base+t+1

__device__ __forceinline__ ull splat2(float v) {
    ull r; asm("mov.b64 %0, {%1, %1};" : "=l"(r) : "f"(v)); return r;
}
__device__ __forceinline__ ull fma2(ull a, ull b, ull c) {
    ull d; asm("fma.rn.f32x2 %0, %1, %2, %3;" : "=l"(d) : "l"(a), "l"(b), "l"(c)); return d;
}
__device__ __forceinline__ ull add2(ull a, ull b) {
    ull d; asm("add.rn.f32x2 %0, %1, %2;" : "=l"(d) : "l"(a), "l"(b)); return d;
}
__device__ __forceinline__ void upk(ull v, float& lo, float& hi) {
    asm("mov.b64 {%0, %1}, %2;" : "=f"(lo), "=f"(hi) : "l"(v));
}
__device__ __forceinline__ ull shflx16(ull v) {
    unsigned lo = (unsigned)v, hi = (unsigned)(v >> 32);
    lo = __shfl_xor_sync(0xffffffffu, lo, 16);
    hi = __shfl_xor_sync(0xffffffffu, hi, 16);
    return ((ull)hi << 32) | lo;
}

// ---------------------------------------------------------------------------
// single persistent kernel: epoch-based flags (no init kernel), t=0 init,
// 255 recurrence steps (R4-proven sync structure), final fold (blocks 0..15)
// ---------------------------------------------------------------------------
__global__ void __launch_bounds__(NTHR, 1) hmm_persist(
    const int* __restrict__ ids, const float* __restrict__ alpha,
    const float* __restrict__ beta, const float* __restrict__ gamma,
    float* __restrict__ out) {
    extern __shared__ float smem[];
    float* s_a = smem;               // [2048][16] alpha slice [k][r] (131072B)
    float* s_part = s_a + H * 16;    // [16 row * 16 b][16 warp] partials (16KB)
    float* s_y = s_part + 256 * 16;  // [256]
    float* s_red = s_y + 256;        // [256]
    float* s_m = s_red + 256;        // [16] shift for publishing E_t  (= m_{t-1})
    float* s_old = s_m + 16;         // [16] shift used in E_{t-1}     (= m_{t-2})

    const int tid = threadIdx.x;
    const int blk = blockIdx.x;
    const int r0 = blk * 16;
    const int lane = tid & 31, w = tid >> 5;
    const int bg = lane & 3;                   // b group: b = bg*4..bg*4+3
    const int rg = (lane >> 2) & 3;            // row group: rows rg*4..rg*4+3
    const int khalf = lane >> 4;               // k parity in warp's 128-k slice
    const int orow = tid >> 4, ob = tid & 15;  // epilogue mapping (tid<256)
    const bool epi = (tid < 256);

    // epoch base: own flag (only this block ever writes it; all equal at entry)
    __shared__ unsigned s_base;
    if (tid == 0) s_base = *(volatile unsigned*)&g_flag[blk];

    // stage alpha slice transposed: s_a[k*16 + rl] = alpha[(r0+rl)*H + k]
    for (int rl = 0; rl < 16; rl++) {
        const float* ap = alpha + (size_t)(r0 + rl) * H;
        for (int k = tid; k < H; k += NTHR) s_a[k * 16 + rl] = __ldg(ap + k);
    }
    if (tid < 16) s_m[tid] = 0.f;
    __syncthreads();
    const unsigned base = s_base;

    // ---- t = 0: y0 = masked beta gather; E_0 = exp(y0) (y0 <= 0, shift 0)
    {
        float y0 = 0.f;
        if (epi) {
            int id = __ldg(&ids[ob * S + (S - 1)]);
            float bv = __ldg(&beta[(size_t)(r0 + orow) * V + (id < 0 ? 0 : id)]);
            y0 = (id < 0) ? 0.f : bv;
            out[(size_t)(r0 + orow) * B + ob] = y0;
            s_y[tid] = y0;
            g_E[0][(r0 + orow) * B + ob] = __expf(y0);
        }
        __syncthreads();
        if (tid < 16) {
            float mx = s_y[tid];
            #pragma unroll
            for (int rr = 1; rr < 16; rr++) mx = fmaxf(mx, s_y[rr * 16 + tid]);
            g_part[0][blk * B + tid] = mx;
        }
        __threadfence();
        __syncthreads();
        if (tid == 0) atomicExch(&g_flag[blk], base + 1u);
    }

    // ---- main recurrence (R4-proven structure)
    for (int t = 1; t < S; t++) {
        const int par = (t - 1) & 1;

        // prefetch ip (independent of any flag)
        float ipv = 0.f;
        if (epi) {
            int id = __ldg(&ids[ob * S + (S - 1 - t)]);
            float bv = __ldg(&beta[(size_t)(r0 + orow) * V + (id < 0 ? 0 : id)]);
            ipv = (id < 0) ? 0.f : bv;
        }

        // flat barrier: all blocks published step t-1
        if (tid < NBLK) {
            volatile unsigned* f = &g_flag[tid];
            const unsigned bt = base + (unsigned)t;
            while (*f < bt) {}
        }
        __syncthreads();

        // s_old <- shift used in E_{t-1};  s_m <- m_{t-1} (for publishing E_t)
        if (tid < 16) s_old[tid] = s_m[tid];
        __syncthreads();
        if (epi) {
            int g = tid >> 4;
            const float* gp = g_part[par];
            float mx = -3.4e38f;
            #pragma unroll
            for (int j = 0; j < 8; j++) mx = fmaxf(mx, __ldcg(gp + (g * 8 + j) * B + ob));
            s_red[g * 16 + ob] = mx;
        }
        __syncthreads();
        if (tid < 16) {
            float mx = s_red[tid];
            #pragma unroll
            for (int g = 1; g < 16; g++) mx = fmaxf(mx, s_red[g * 16 + tid]);
            s_m[tid] = mx;
        }

        // ---- dot: acc[rowlane][bpair] over this warp's 128 k (64 per khalf)
        const float* Eg = g_E[par];
        ull acc[4][2];
        #pragma unroll
        for (int l = 0; l < 4; l++) { acc[l][0] = 0ull; acc[l][1] = 0ull; }

        const int kbase = w * 128 + khalf;
        #pragma unroll 8
        for (int i = 0; i < 64; i++) {
            const int k = kbase + 2 * i;
            ulonglong2 ev = __ldcg(reinterpret_cast<const ulonglong2*>(Eg + k * B + bg * 4));
            float4 av = *reinterpret_cast<const float4*>(s_a + k * 16 + rg * 4);
            const ull a0 = splat2(av.x), a1 = splat2(av.y);
            const ull a2 = splat2(av.z), a3 = splat2(av.w);
            acc[0][0] = fma2(a0, ev.x, acc[0][0]);
            acc[0][1] = fma2(a0, ev.y, acc[0][1]);
            acc[1][0] = fma2(a1, ev.x, acc[1][0]);
            acc[1][1] = fma2(a1, ev.y, acc[1][1]);
            acc[2][0] = fma2(a2, ev.x, acc[2][0]);
            acc[2][1] = fma2(a2, ev.y, acc[2][1]);
            acc[3][0] = fma2(a3, ev.x, acc[3][0]);
            acc[3][1] = fma2(a3, ev.y, acc[3][1]);
        }

        // combine khalf halves, store partials
        #pragma unroll
        for (int l = 0; l < 4; l++) {
            acc[l][0] = add2(acc[l][0], shflx16(acc[l][0]));
            acc[l][1] = add2(acc[l][1], shflx16(acc[l][1]));
        }
        if (khalf == 0) {
            #pragma unroll
            for (int l = 0; l < 4; l++) {
                float f0, f1;
                upk(acc[l][0], f0, f1);
                s_part[((rg * 4 + l) * 16 + bg * 4 + 0) * 16 + w] = f0;
                s_part[((rg * 4 + l) * 16 + bg * 4 + 1) * 16 + w] = f1;
                upk(acc[l][1], f0, f1);
                s_part[((rg * 4 + l) * 16 + bg * 4 + 2) * 16 + w] = f0;
                s_part[((rg * 4 + l) * 16 + bg * 4 + 3) * 16 + w] = f1;
            }
        }
        __syncthreads();

        // epilogue: y = log(sum) + m_{t-2} + ip;  E_t = exp(y - m_{t-1})
        float y = 0.f;
        if (epi) {
            const float* pp = s_part + tid * 16;
            float sum = 0.f;
            #pragma unroll
            for (int c = 0; c < 16; c++) sum += pp[c];
            y = __logf(sum) + s_old[ob] + ipv;
            out[(size_t)t * H * B + (size_t)(r0 + orow) * B + ob] = y;
            s_y[tid] = y;
            g_E[t & 1][(r0 + orow) * B + ob] = __expf(y - s_m[ob]);
        }
        __syncthreads();
        if (tid < 16) {
            float mx = s_y[tid];
            #pragma unroll
            for (int rr = 1; rr < 16; rr++) mx = fmaxf(mx, s_y[rr * 16 + tid]);
            g_part[t & 1][blk * B + tid] = mx;
        }
        __threadfence();
        __syncthreads();
        if (tid == 0) atomicExch(&g_flag[blk], base + (unsigned)(t + 1));
    }

    // ---- final fold: block b (<16) computes final[b].
    //      E_{S-1} = exp(y_{S-1} - m_{S-2});  m_{S-2} lives in g_part[(S-2)&1] = [0]
    //      final[b] = log( sum_h softmax(gamma)_h * E[h,b] ) + m_{S-2,b}
    if (blk < 16) {
        if (tid < NBLK) {
            volatile unsigned* f = &g_flag[tid];
            const unsigned bs = base + (unsigned)S;
            while (*f < bs) {}
        }
        __syncthreads();

        // gamma stats (softmax denominator), block-wide
        float gv[4];
        #pragma unroll
        for (int i = 0; i < 4; i++) gv[i] = __ldg(&gamma[tid + i * NTHR]);
        float gm = fmaxf(fmaxf(gv[0], gv[1]), fmaxf(gv[2], gv[3]));
        #pragma unroll
        for (int o = 16; o > 0; o >>= 1)
            gm = fmaxf(gm, __shfl_xor_sync(0xffffffffu, gm, o));
        if (lane == 0) s_red[w] = gm;
        __syncthreads();
        float gmax = s_red[0];
        #pragma unroll
        for (int c = 1; c < 16; c++) gmax = fmaxf(gmax, s_red[c]);

        // qs = sum exp(gamma - gmax);  sm = sum exp(gamma - gmax) * E[h,b]
        const float* El = g_E[(S - 1) & 1];
        float qs = 0.f, sm = 0.f;
        #pragma unroll
        for (int i = 0; i < 4; i++) {
            int h = tid + i * NTHR;
            float q = __expf(gv[i] - gmax);
            qs += q;
            sm += q * __ldcg(El + (size_t)h * B + blk);
        }
        #pragma unroll
        for (int o = 16; o > 0; o >>= 1) {
            qs += __shfl_xor_sync(0xffffffffu, qs, o);
            sm += __shfl_xor_sync(0xffffffffu, sm, o);
        }
        if (lane == 0) { s_y[w] = qs; s_red[16 + w] = sm; }

        // M = m_{S-2, b}: max over 128 blocks' row maxes (buffer 0)
        if (w < 4) {  // tid < 128 exactly
            float mv = __ldcg(g_part[0] + tid * B + blk);
            #pragma unroll
            for (int o = 16; o > 0; o >>= 1)
                mv = fmaxf(mv, __shfl_xor_sync(0xffffffffu, mv, o));
            if (lane == 0) s_y[32 + w] = mv;
        }
        __syncthreads();

        if (tid == 0) {
            float gsum = 0.f, tot = 0.f;
            #pragma unroll
            for (int c = 0; c < 16; c++) { gsum += s_y[c]; tot += s_red[16 + c]; }
            float M = fmaxf(fmaxf(s_y[32], s_y[33]), fmaxf(s_y[34], s_y[35]));
            out[(size_t)S * H * B + blk] = __logf(tot) - __logf(gsum) + M;
        }
    }
}

// ---------------------------------------------------------------------------
extern "C" void kernel_launch(void* const* d_in, const int* in_sizes, int n_in,
                              void* d_out, int out_size) {
    const int* ids = (const int*)d_in[0];        // (B, S) int32
    const float* alpha = (const float*)d_in[1];  // (H, H)
    const float* beta = (const float*)d_in[2];   // (H, V)
    const float* gamma = (const float*)d_in[3];  // (H,)
    float* out = (float*)d_out;                  // ys (S,H,B) then final (B,)

    const int smem_main =
        (H * 16 + 256 * 16 + 256 + 256 + 16 + 16) * (int)sizeof(float);
    cudaFuncSetAttribute(hmm_persist, cudaFuncAttributeMaxDynamicSharedMemorySize,
                         smem_main);

    hmm_persist<<<NBLK, NTHR, smem_main>>>(ids, alpha, beta, gamma, out);
}

// round 11
// speedup vs baseline: 2.1715x; 1.3710x over previous
#include <cuda_runtime.h>
#include <cstdint>

#define H 2048
#define B 16
#define S 256
#define V 32000
#define NBLK 128
#define NTHR 512
#define PPAD 17

typedef unsigned long long ull;

__device__ float g_E[2][H * B];     // exp(y_t - shift_t), double buffered by t&1
__device__ float g_shift[2][B];     // shift_t[b] = y_t[0,b] (block 0, row 0)
__device__ unsigned g_flag[NBLK];   // monotonic epochs: done step t => base+t+1

__device__ __forceinline__ ull splat2(float v) {
    ull r; asm("mov.b64 %0, {%1, %1};" : "=l"(r) : "f"(v)); return r;
}
__device__ __forceinline__ ull fma2(ull a, ull b, ull c) {
    ull d; asm("fma.rn.f32x2 %0, %1, %2, %3;" : "=l"(d) : "l"(a), "l"(b), "l"(c)); return d;
}
__device__ __forceinline__ ull add2(ull a, ull b) {
    ull d; asm("add.rn.f32x2 %0, %1, %2;" : "=l"(d) : "l"(a), "l"(b)); return d;
}
__device__ __forceinline__ void upk(ull v, float& lo, float& hi) {
    asm("mov.b64 {%0, %1}, %2;" : "=f"(lo), "=f"(hi) : "l"(v));
}
__device__ __forceinline__ ull shflx16(ull v) {
    unsigned lo = (unsigned)v, hi = (unsigned)(v >> 32);
    lo = __shfl_xor_sync(0xffffffffu, lo, 16);
    hi = __shfl_xor_sync(0xffffffffu, hi, 16);
    return ((ull)hi << 32) | lo;
}
__device__ __forceinline__ void atom_rel_exch(unsigned* p, unsigned v) {
    unsigned old;
    asm volatile("atom.release.gpu.global.exch.b32 %0, [%1], %2;"
                 : "=r"(old) : "l"(p), "r"(v) : "memory");
}

// ---------------------------------------------------------------------------
// single persistent kernel: epoch flags, t=0 init, 255 steps, final fold
// ---------------------------------------------------------------------------
__global__ void __launch_bounds__(NTHR, 1) hmm_persist(
    const int* __restrict__ ids, const float* __restrict__ alpha,
    const float* __restrict__ beta, const float* __restrict__ gamma,
    float* __restrict__ out) {
    extern __shared__ float smem[];
    float* s_a = smem;               // [2048][16] alpha slice [k][r] (131072B)
    float* s_part = s_a + H * 16;    // [256 rows*b][PPAD] partials (padded)
    float* s_misc = s_part + 256 * PPAD;  // [128] staging for final fold

    const int tid = threadIdx.x;
    const int blk = blockIdx.x;
    const int r0 = blk * 16;
    const int lane = tid & 31, w = tid >> 5;
    const int bg = lane & 3;                   // b group: b = bg*4..bg*4+3
    const int rg = (lane >> 2) & 3;            // row group: rows rg*4..rg*4+3
    const int khalf = lane >> 4;               // k parity in warp's 128-k slice
    const int orow = tid >> 4, ob = tid & 15;  // epilogue mapping (tid<256)
    const bool epi = (tid < 256);

    // epoch base: own flag (only this block writes it; all flags equal at entry)
    __shared__ unsigned s_base;
    if (tid == 0) s_base = *(volatile unsigned*)&g_flag[blk];

    // stage alpha slice transposed: s_a[k*16 + rl] = alpha[(r0+rl)*H + k]
    for (int rl = 0; rl < 16; rl++) {
        const float* ap = alpha + (size_t)(r0 + rl) * H;
        for (int k = tid; k < H; k += NTHR) s_a[k * 16 + rl] = __ldg(ap + k);
    }
    __syncthreads();
    const unsigned base = s_base;

    float m_prev = 0.f;  // shift used when E_{t-1} was published

    // ---- t = 0: y0 = masked beta gather; E_0 = exp(y0) (y0 <= 0, shift 0)
    {
        float y0 = 0.f;
        if (epi) {
            int id = __ldg(&ids[ob * S + (S - 1)]);
            float bv = __ldg(&beta[(size_t)(r0 + orow) * V + (id < 0 ? 0 : id)]);
            y0 = (id < 0) ? 0.f : bv;
            g_E[0][(r0 + orow) * B + ob] = __expf(y0);
            if (blk == 0 && tid < 16) g_shift[0][tid] = y0;  // y0[row 0, b]
        }
        __syncthreads();
        if (tid == 0) atom_rel_exch(&g_flag[blk], base + 1u);
        if (epi) out[(size_t)(r0 + orow) * B + ob] = y0;
    }

    // ---- main recurrence
    for (int t = 1; t < S; t++) {
        const int par = (t - 1) & 1;

        // prefetch ip (independent of any flag)
        float ipv = 0.f;
        if (epi) {
            int id = __ldg(&ids[ob * S + (S - 1 - t)]);
            float bv = __ldg(&beta[(size_t)(r0 + orow) * V + (id < 0 ? 0 : id)]);
            ipv = (id < 0) ? 0.f : bv;
        }

        // flat barrier: all blocks published step t-1 (R4-proven spin)
        if (tid < NBLK) {
            volatile unsigned* f = &g_flag[tid];
            const unsigned bt = base + (unsigned)t;
            while (*f < bt) {}
        }
        __syncthreads();

        // new shift for publishing E_t: y_{t-1}[0, b] (single 64B line; latency
        // hides under the dot)
        float Mb = 0.f;
        if (epi) Mb = __ldcg(&g_shift[par][ob]);

        // ---- dot: acc[rowlane][bpair] over this warp's 128 k (64 per khalf)
        const float* Eg = g_E[par];
        ull acc[4][2];
        #pragma unroll
        for (int l = 0; l < 4; l++) { acc[l][0] = 0ull; acc[l][1] = 0ull; }

        const int kbase = w * 128 + khalf;
        #pragma unroll 8
        for (int i = 0; i < 64; i++) {
            const int k = kbase + 2 * i;
            ulonglong2 ev = __ldcg(reinterpret_cast<const ulonglong2*>(Eg + k * B + bg * 4));
            float4 av = *reinterpret_cast<const float4*>(s_a + k * 16 + rg * 4);
            const ull a0 = splat2(av.x), a1 = splat2(av.y);
            const ull a2 = splat2(av.z), a3 = splat2(av.w);
            acc[0][0] = fma2(a0, ev.x, acc[0][0]);
            acc[0][1] = fma2(a0, ev.y, acc[0][1]);
            acc[1][0] = fma2(a1, ev.x, acc[1][0]);
            acc[1][1] = fma2(a1, ev.y, acc[1][1]);
            acc[2][0] = fma2(a2, ev.x, acc[2][0]);
            acc[2][1] = fma2(a2, ev.y, acc[2][1]);
            acc[3][0] = fma2(a3, ev.x, acc[3][0]);
            acc[3][1] = fma2(a3, ev.y, acc[3][1]);
        }

        // combine khalf halves, store partials ([row*16+b][w], PPAD-padded)
        #pragma unroll
        for (int l = 0; l < 4; l++) {
            acc[l][0] = add2(acc[l][0], shflx16(acc[l][0]));
            acc[l][1] = add2(acc[l][1], shflx16(acc[l][1]));
        }
        if (khalf == 0) {
            #pragma unroll
            for (int l = 0; l < 4; l++) {
                float f0, f1;
                upk(acc[l][0], f0, f1);
                s_part[((rg * 4 + l) * 16 + bg * 4 + 0) * PPAD + w] = f0;
                s_part[((rg * 4 + l) * 16 + bg * 4 + 1) * PPAD + w] = f1;
                upk(acc[l][1], f0, f1);
                s_part[((rg * 4 + l) * 16 + bg * 4 + 2) * PPAD + w] = f0;
                s_part[((rg * 4 + l) * 16 + bg * 4 + 3) * PPAD + w] = f1;
            }
        }
        __syncthreads();

        // epilogue: y = log(sum) + m_prev + ip;  E_t = exp(y - Mb)
        float y = 0.f;
        if (epi) {
            const float* pp = s_part + tid * PPAD;  // conflict-free (17 odd)
            float sum = 0.f;
            #pragma unroll
            for (int c = 0; c < 16; c++) sum += pp[c];
            y = __logf(sum) + m_prev + ipv;
            g_E[t & 1][(r0 + orow) * B + ob] = __expf(y - Mb);
            if (blk == 0 && tid < 16) g_shift[t & 1][tid] = y;  // y_t[0, b]
            m_prev = Mb;
        }
        __syncthreads();
        if (tid == 0) atom_rel_exch(&g_flag[blk], base + (unsigned)(t + 1));

        // ys store off the critical path
        if (epi) out[(size_t)t * H * B + (size_t)(r0 + orow) * B + ob] = y;
    }

    // ---- final fold: block b (<16) computes final[b].
    //      E_{S-1} = exp(y_{S-1} - shift) with shift = g_shift[(S-2)&1][b]
    //      final[b] = log( sum_h softmax(gamma)_h * E[h,b] ) + shift
    if (blk < 16) {
        if (tid < NBLK) {
            volatile unsigned* f = &g_flag[tid];
            const unsigned bs = base + (unsigned)S;
            while (*f < bs) {}
        }
        __syncthreads();

        // gamma softmax stats, block-wide
        float gv[4];
        #pragma unroll
        for (int i = 0; i < 4; i++) gv[i] = __ldg(&gamma[tid + i * NTHR]);
        float gm = fmaxf(fmaxf(gv[0], gv[1]), fmaxf(gv[2], gv[3]));
        #pragma unroll
        for (int o = 16; o > 0; o >>= 1)
            gm = fmaxf(gm, __shfl_xor_sync(0xffffffffu, gm, o));
        if (lane == 0) s_misc[64 + w] = gm;
        __syncthreads();
        float gmax = s_misc[64];
        #pragma unroll
        for (int c = 1; c < 16; c++) gmax = fmaxf(gmax, s_misc[64 + c]);

        const float* El = g_E[(S - 1) & 1];
        float qs = 0.f, sm = 0.f;
        #pragma unroll
        for (int i = 0; i < 4; i++) {
            int h = tid + i * NTHR;
            float q = __expf(gv[i] - gmax);
            qs += q;
            sm += q * __ldcg(El + (size_t)h * B + blk);
        }
        #pragma unroll
        for (int o = 16; o > 0; o >>= 1) {
            qs += __shfl_xor_sync(0xffffffffu, qs, o);
            sm += __shfl_xor_sync(0xffffffffu, sm, o);
        }
        if (lane == 0) { s_misc[w] = qs; s_misc[32 + w] = sm; }
        __syncthreads();

        if (tid == 0) {
            float gsum = 0.f, tot = 0.f;
            #pragma unroll
            for (int c = 0; c < 16; c++) { gsum += s_misc[c]; tot += s_misc[32 + c]; }
            float shift = __ldcg(&g_shift[(S - 2) & 1][blk]);
            out[(size_t)S * H * B + blk] = __logf(tot) - __logf(gsum) + shift;
        }
    }
}

// ---------------------------------------------------------------------------
extern "C" void kernel_launch(void* const* d_in, const int* in_sizes, int n_in,
                              void* d_out, int out_size) {
    const int* ids = (const int*)d_in[0];        // (B, S) int32
    const float* alpha = (const float*)d_in[1];  // (H, H)
    const float* beta = (const float*)d_in[2];   // (H, V)
    const float* gamma = (const float*)d_in[3];  // (H,)
    float* out = (float*)d_out;                  // ys (S,H,B) then final (B,)

    const int smem_main = (H * 16 + 256 * PPAD + 128) * (int)sizeof(float);
    cudaFuncSetAttribute(hmm_persist, cudaFuncAttributeMaxDynamicSharedMemorySize,
                         smem_main);

    hmm_persist<<<NBLK, NTHR, smem_main>>>(ids, alpha, beta, gamma, out);
}

// round 12
// speedup vs baseline: 3.3723x; 1.5530x over previous
#include <cuda_runtime.h>
#include <cstdint>

#define H 2048
#define B 16
#define S 256
#define V 32000
#define NBLK 128
#define NTHR 512
#define PPAD 17

__device__ float g_E[2][H * B];    // tf32-rounded exp(y_t - shift_t), dbl buffered
__device__ float g_shift[2][B];    // shift_t[b] = y_t[0,b] (block 0, row 0)
__device__ unsigned g_flag[NBLK];  // monotonic epochs: done step t => base+t+1

__device__ __forceinline__ unsigned cvt_tf32(float f) {
    unsigned r; asm("cvt.rna.tf32.f32 %0, %1;" : "=r"(r) : "f"(f)); return r;
}
__device__ __forceinline__ void mma_tf32(float* d, const unsigned* a,
                                         const unsigned* b, const float* c) {
    asm("mma.sync.aligned.m16n8k8.row.col.f32.tf32.tf32.f32 "
        "{%0,%1,%2,%3}, {%4,%5,%6,%7}, {%8,%9}, {%10,%11,%12,%13};"
        : "=f"(d[0]), "=f"(d[1]), "=f"(d[2]), "=f"(d[3])
        : "r"(a[0]), "r"(a[1]), "r"(a[2]), "r"(a[3]),
          "r"(b[0]), "r"(b[1]),
          "f"(c[0]), "f"(c[1]), "f"(c[2]), "f"(c[3]));
}
__device__ __forceinline__ void atom_rel_exch(unsigned* p, unsigned v) {
    unsigned old;
    asm volatile("atom.release.gpu.global.exch.b32 %0, [%1], %2;"
                 : "=r"(old) : "l"(p), "r"(v) : "memory");
}

// ---------------------------------------------------------------------------
// single persistent kernel: epoch flags, alpha in MMA register fragments,
// t=0 init, 255 tf32-MMA steps, final fold (blocks 0..15)
// ---------------------------------------------------------------------------
__global__ void __launch_bounds__(NTHR, 1) hmm_persist(
    const int* __restrict__ ids, const float* __restrict__ alpha,
    const float* __restrict__ beta, const float* __restrict__ gamma,
    float* __restrict__ out) {
    extern __shared__ float smem[];
    float* s_part = smem;                  // [256][PPAD] cross-warp partials
    float* s_misc = s_part + 256 * PPAD;   // [128] staging

    const int tid = threadIdx.x;
    const int blk = blockIdx.x;
    const int r0 = blk * 16;
    const int lane = tid & 31, w = tid >> 5;
    const int gid = lane >> 2;                 // MMA group id (0..7)
    const int tg = lane & 3;                   // thread-in-group (0..3)
    const int orow = tid >> 4, ob = tid & 15;  // epilogue mapping (tid<256)
    const bool epi = (tid < 256);
    const int kb = w * 128;                    // this warp's k slice

    __shared__ unsigned s_base;
    if (tid == 0) s_base = *(volatile unsigned*)&g_flag[blk];

    // preload alpha MMA A-fragments (m16 rows = this block's 16 outputs,
    // k = warp's 128-slice): afr[kt][i], rows {gid, gid+8}, cols {tg, tg+4}
    unsigned afr[16][4];
    #pragma unroll
    for (int kt = 0; kt < 16; kt++) {
        const int k0 = kb + kt * 8;
        afr[kt][0] = cvt_tf32(__ldg(&alpha[(size_t)(r0 + gid) * H + k0 + tg]));
        afr[kt][1] = cvt_tf32(__ldg(&alpha[(size_t)(r0 + gid + 8) * H + k0 + tg]));
        afr[kt][2] = cvt_tf32(__ldg(&alpha[(size_t)(r0 + gid) * H + k0 + tg + 4]));
        afr[kt][3] = cvt_tf32(__ldg(&alpha[(size_t)(r0 + gid + 8) * H + k0 + tg + 4]));
    }
    __syncthreads();
    const unsigned base = s_base;

    float m_prev = 0.f;  // shift used when E_{t-1} was published

    // ---- t = 0: y0 = masked beta gather; E_0 = tf32(exp(y0))
    {
        float y0 = 0.f;
        if (epi) {
            int id = __ldg(&ids[ob * S + (S - 1)]);
            float bv = __ldg(&beta[(size_t)(r0 + orow) * V + (id < 0 ? 0 : id)]);
            y0 = (id < 0) ? 0.f : bv;
            g_E[0][(r0 + orow) * B + ob] = __uint_as_float(cvt_tf32(__expf(y0)));
            if (blk == 0 && tid < 16) g_shift[0][tid] = y0;
        }
        __syncthreads();
        if (tid == 0) atom_rel_exch(&g_flag[blk], base + 1u);
        if (epi) out[(size_t)(r0 + orow) * B + ob] = y0;
    }

    // ---- main recurrence
    for (int t = 1; t < S; t++) {
        const int par = (t - 1) & 1;

        // prefetch ip (independent of any flag)
        float ipv = 0.f;
        if (epi) {
            int id = __ldg(&ids[ob * S + (S - 1 - t)]);
            float bv = __ldg(&beta[(size_t)(r0 + orow) * V + (id < 0 ? 0 : id)]);
            ipv = (id < 0) ? 0.f : bv;
        }

        // flat barrier: all blocks published step t-1
        if (tid < NBLK) {
            volatile unsigned* f = &g_flag[tid];
            const unsigned bt = base + (unsigned)t;
            while (*f < bt) {}
        }
        __syncthreads();

        // shift for publishing E_t (one 64B line, hides under the dot)
        float Mb = 0.f;
        if (epi) Mb = __ldcg(&g_shift[par][ob]);

        // ---- tf32 MMA dot: D[16 x 16] over this warp's 128 k
        const float* Eg = g_E[par];
        float acc0[4] = {0.f, 0.f, 0.f, 0.f};  // cols 0..7
        float acc1[4] = {0.f, 0.f, 0.f, 0.f};  // cols 8..15
        #pragma unroll
        for (int kt = 0; kt < 16; kt++) {
            const int kr = kb + kt * 8 + tg;
            unsigned b0[2], b1[2];
            b0[0] = __float_as_uint(__ldcg(&Eg[kr * B + gid]));
            b0[1] = __float_as_uint(__ldcg(&Eg[(kr + 4) * B + gid]));
            b1[0] = __float_as_uint(__ldcg(&Eg[kr * B + 8 + gid]));
            b1[1] = __float_as_uint(__ldcg(&Eg[(kr + 4) * B + 8 + gid]));
            mma_tf32(acc0, afr[kt], b0, acc0);
            mma_tf32(acc1, afr[kt], b1, acc1);
        }

        // store partials: rows {gid, gid+8}, cols {2tg, 2tg+1} (+8 for acc1)
        s_part[(gid * 16 + 2 * tg) * PPAD + w] = acc0[0];
        s_part[(gid * 16 + 2 * tg + 1) * PPAD + w] = acc0[1];
        s_part[((gid + 8) * 16 + 2 * tg) * PPAD + w] = acc0[2];
        s_part[((gid + 8) * 16 + 2 * tg + 1) * PPAD + w] = acc0[3];
        s_part[(gid * 16 + 8 + 2 * tg) * PPAD + w] = acc1[0];
        s_part[(gid * 16 + 8 + 2 * tg + 1) * PPAD + w] = acc1[1];
        s_part[((gid + 8) * 16 + 8 + 2 * tg) * PPAD + w] = acc1[2];
        s_part[((gid + 8) * 16 + 8 + 2 * tg + 1) * PPAD + w] = acc1[3];
        __syncthreads();

        // epilogue: y = log(sum16) + m_prev + ip;  E_t = tf32(exp(y - Mb))
        float y = 0.f;
        if (epi) {
            const float* pp = s_part + tid * PPAD;
            float sum = 0.f;
            #pragma unroll
            for (int c = 0; c < 16; c++) sum += pp[c];
            y = __logf(sum) + m_prev + ipv;
            g_E[t & 1][(r0 + orow) * B + ob] = __uint_as_float(cvt_tf32(__expf(y - Mb)));
            if (blk == 0 && tid < 16) g_shift[t & 1][tid] = y;
            m_prev = Mb;
        }
        __syncthreads();
        if (tid == 0) atom_rel_exch(&g_flag[blk], base + (unsigned)(t + 1));

        // ys store off the critical path
        if (epi) out[(size_t)t * H * B + (size_t)(r0 + orow) * B + ob] = y;
    }

    // ---- final fold: block b (<16): final[b] = log(sum_h softmax(gamma)_h *
    //      E_{S-1}[h,b]) + g_shift[(S-2)&1][b]
    if (blk < 16) {
        if (tid < NBLK) {
            volatile unsigned* f = &g_flag[tid];
            const unsigned bs = base + (unsigned)S;
            while (*f < bs) {}
        }
        __syncthreads();

        float gv[4];
        #pragma unroll
        for (int i = 0; i < 4; i++) gv[i] = __ldg(&gamma[tid + i * NTHR]);
        float gm = fmaxf(fmaxf(gv[0], gv[1]), fmaxf(gv[2], gv[3]));
        #pragma unroll
        for (int o = 16; o > 0; o >>= 1)
            gm = fmaxf(gm, __shfl_xor_sync(0xffffffffu, gm, o));
        if (lane == 0) s_misc[64 + w] = gm;
        __syncthreads();
        float gmax = s_misc[64];
        #pragma unroll
        for (int c = 1; c < 16; c++) gmax = fmaxf(gmax, s_misc[64 + c]);

        const float* El = g_E[(S - 1) & 1];
        float qs = 0.f, sm = 0.f;
        #pragma unroll
        for (int i = 0; i < 4; i++) {
            int h = tid + i * NTHR;
            float q = __expf(gv[i] - gmax);
            qs += q;
            sm += q * __ldcg(El + (size_t)h * B + blk);
        }
        #pragma unroll
        for (int o = 16; o > 0; o >>= 1) {
            qs += __shfl_xor_sync(0xffffffffu, qs, o);
            sm += __shfl_xor_sync(0xffffffffu, sm, o);
        }
        if (lane == 0) { s_misc[w] = qs; s_misc[32 + w] = sm; }
        __syncthreads();

        if (tid == 0) {
            float gsum = 0.f, tot = 0.f;
            #pragma unroll
            for (int c = 0; c < 16; c++) { gsum += s_misc[c]; tot += s_misc[32 + c]; }
            float shift = __ldcg(&g_shift[(S - 2) & 1][blk]);
            out[(size_t)S * H * B + blk] = __logf(tot) - __logf(gsum) + shift;
        }
    }
}

// ---------------------------------------------------------------------------
extern "C" void kernel_launch(void* const* d_in, const int* in_sizes, int n_in,
                              void* d_out, int out_size) {
    const int* ids = (const int*)d_in[0];        // (B, S) int32
    const float* alpha = (const float*)d_in[1];  // (H, H)
    const float* beta = (const float*)d_in[2];   // (H, V)
    const float* gamma = (const float*)d_in[3];  // (H,)
    float* out = (float*)d_out;                  // ys (S,H,B) then final (B,)

    const int smem_main = (256 * PPAD + 128) * (int)sizeof(float);
    cudaFuncSetAttribute(hmm_persist, cudaFuncAttributeMaxDynamicSharedMemorySize,
                         smem_main);

    hmm_persist<<<NBLK, NTHR, smem_main>>>(ids, alpha, beta, gamma, out);
}

// round 13
// speedup vs baseline: 3.8310x; 1.1360x over previous
#include <cuda_runtime.h>
#include <cstdint>

#define H 2048
#define B 16
#define S 256
#define V 32000
#define NBLK 128
#define NTHR 512
#define PPAD 17

__device__ float g_E[2][H * B];    // tf32-rounded exp(y_t - shift_t), dbl buffered
__device__ float g_shift[2][B];    // shift_t[b] = y_t[0,b] (block 0, row 0)
__device__ unsigned g_flag[NBLK];  // monotonic epochs: done step t => base+t+1

__device__ __forceinline__ unsigned cvt_tf32(float f) {
    unsigned r; asm("cvt.rna.tf32.f32 %0, %1;" : "=r"(r) : "f"(f)); return r;
}
__device__ __forceinline__ void mma_tf32(float* d, const unsigned* a,
                                         const unsigned* b, const float* c) {
    asm("mma.sync.aligned.m16n8k8.row.col.f32.tf32.tf32.f32 "
        "{%0,%1,%2,%3}, {%4,%5,%6,%7}, {%8,%9}, {%10,%11,%12,%13};"
        : "=f"(d[0]), "=f"(d[1]), "=f"(d[2]), "=f"(d[3])
        : "r"(a[0]), "r"(a[1]), "r"(a[2]), "r"(a[3]),
          "r"(b[0]), "r"(b[1]),
          "f"(c[0]), "f"(c[1]), "f"(c[2]), "f"(c[3]));
}
__device__ __forceinline__ void atom_rel_exch(unsigned* p, unsigned v) {
    unsigned old;
    asm volatile("atom.release.gpu.global.exch.b32 %0, [%1], %2;"
                 : "=r"(old) : "l"(p), "r"(v) : "memory");
}

// ---------------------------------------------------------------------------
// single persistent kernel: epoch flags, alpha in MMA register fragments,
// critical path free of log/exp: E_t = sum * exp(ip + m_prev - Mb)
// ---------------------------------------------------------------------------
__global__ void __launch_bounds__(NTHR, 1) hmm_persist(
    const int* __restrict__ ids, const float* __restrict__ alpha,
    const float* __restrict__ beta, const float* __restrict__ gamma,
    float* __restrict__ out) {
    extern __shared__ float smem[];
    float* s_part = smem;                 // [256][PPAD] cross-warp partials
    float* s_misc = s_part + 256 * PPAD;  // [128] staging

    const int tid = threadIdx.x;
    const int blk = blockIdx.x;
    const int r0 = blk * 16;
    const int lane = tid & 31, w = tid >> 5;
    const int gid = lane >> 2;                 // MMA group id (0..7)
    const int tg = lane & 3;                   // thread-in-group (0..3)
    const int orow = tid >> 4, ob = tid & 15;  // epilogue mapping (tid<256)
    const bool epi = (tid < 256);
    const int kb = w * 128;                    // this warp's k slice

    __shared__ unsigned s_base;
    if (tid == 0) s_base = *(volatile unsigned*)&g_flag[blk];

    // preload alpha MMA A-fragments: rows {gid, gid+8}, cols {tg, tg+4} per ktile
    unsigned afr[16][4];
    #pragma unroll
    for (int kt = 0; kt < 16; kt++) {
        const int k0 = kb + kt * 8;
        afr[kt][0] = cvt_tf32(__ldg(&alpha[(size_t)(r0 + gid) * H + k0 + tg]));
        afr[kt][1] = cvt_tf32(__ldg(&alpha[(size_t)(r0 + gid + 8) * H + k0 + tg]));
        afr[kt][2] = cvt_tf32(__ldg(&alpha[(size_t)(r0 + gid) * H + k0 + tg + 4]));
        afr[kt][3] = cvt_tf32(__ldg(&alpha[(size_t)(r0 + gid + 8) * H + k0 + tg + 4]));
    }
    __syncthreads();
    const unsigned base = s_base;

    float m_prev = 0.f;  // shift used when E_{t-1} was published

    // ---- t = 0: y0 = masked beta gather; E_0 = tf32(exp(y0))
    {
        float y0 = 0.f;
        if (epi) {
            int id = __ldg(&ids[ob * S + (S - 1)]);
            float bv = __ldg(&beta[(size_t)(r0 + orow) * V + (id < 0 ? 0 : id)]);
            y0 = (id < 0) ? 0.f : bv;
            g_E[0][(r0 + orow) * B + ob] = __uint_as_float(cvt_tf32(__expf(y0)));
            if (blk == 0 && tid < 16) g_shift[0][tid] = y0;
        }
        __syncthreads();
        if (tid == 0) atom_rel_exch(&g_flag[blk], base + 1u);
        if (epi) out[(size_t)(r0 + orow) * B + ob] = y0;
    }

    // ---- main recurrence
    for (int t = 1; t < S; t++) {
        const int par = (t - 1) & 1;

        // prefetch ip (independent of any flag)
        float ipv = 0.f;
        if (epi) {
            int id = __ldg(&ids[ob * S + (S - 1 - t)]);
            float bv = __ldg(&beta[(size_t)(r0 + orow) * V + (id < 0 ? 0 : id)]);
            ipv = (id < 0) ? 0.f : bv;
        }

        // flat barrier: all blocks published step t-1
        if (tid < NBLK) {
            volatile unsigned* f = &g_flag[tid];
            const unsigned bt = base + (unsigned)t;
            while (*f < bt) {}
        }
        __syncthreads();

        // shift for publishing E_t; precompute the E scale during the dot:
        // E_t = sum * exp(ip + m_prev - Mb)
        float Mb = 0.f, scale = 0.f;
        if (epi) {
            Mb = __ldcg(&g_shift[par][ob]);
            scale = __expf(ipv + m_prev - Mb);
        }

        // ---- tf32 MMA dot: D[16 x 16] over this warp's 128 k
        const float* Eg = g_E[par];
        float acc0[4] = {0.f, 0.f, 0.f, 0.f};  // cols 0..7
        float acc1[4] = {0.f, 0.f, 0.f, 0.f};  // cols 8..15
        #pragma unroll
        for (int kt = 0; kt < 16; kt++) {
            const int kr = kb + kt * 8 + tg;
            unsigned b0[2], b1[2];
            b0[0] = __float_as_uint(__ldcg(&Eg[kr * B + gid]));
            b0[1] = __float_as_uint(__ldcg(&Eg[(kr + 4) * B + gid]));
            b1[0] = __float_as_uint(__ldcg(&Eg[kr * B + 8 + gid]));
            b1[1] = __float_as_uint(__ldcg(&Eg[(kr + 4) * B + 8 + gid]));
            mma_tf32(acc0, afr[kt], b0, acc0);
            mma_tf32(acc1, afr[kt], b1, acc1);
        }

        // store partials: rows {gid, gid+8}, cols {2tg, 2tg+1} (+8 for acc1)
        s_part[(gid * 16 + 2 * tg) * PPAD + w] = acc0[0];
        s_part[(gid * 16 + 2 * tg + 1) * PPAD + w] = acc0[1];
        s_part[((gid + 8) * 16 + 2 * tg) * PPAD + w] = acc0[2];
        s_part[((gid + 8) * 16 + 2 * tg + 1) * PPAD + w] = acc0[3];
        s_part[(gid * 16 + 8 + 2 * tg) * PPAD + w] = acc1[0];
        s_part[(gid * 16 + 8 + 2 * tg + 1) * PPAD + w] = acc1[1];
        s_part[((gid + 8) * 16 + 8 + 2 * tg) * PPAD + w] = acc1[2];
        s_part[((gid + 8) * 16 + 8 + 2 * tg + 1) * PPAD + w] = acc1[3];
        __syncthreads();

        // fast epilogue: E_t = sum * scale (no log/exp on the chain)
        float sum = 0.f;
        if (epi) {
            const float* pp = s_part + tid * PPAD;
            #pragma unroll
            for (int c = 0; c < 16; c++) sum += pp[c];
            g_E[t & 1][(r0 + orow) * B + ob] =
                __uint_as_float(cvt_tf32(sum * scale));
            if (blk == 0 && tid < 16) {
                // y_t[0,b] = log(sum) + m_prev + ip — needed as next shift.
                // Small serial cost, block 0 rows only, overlapped by others.
                g_shift[t & 1][tid] = __logf(sum) + m_prev + ipv;
            }
            // release after the 8 epilogue warps' stores (warps 8-15 not needed)
            asm volatile("bar.sync 1, 256;" ::: "memory");
            if (tid == 0) atom_rel_exch(&g_flag[blk], base + (unsigned)(t + 1));
        }

        // ys store + log: fully off the critical path
        if (epi) {
            float y = __logf(sum) + m_prev + ipv;
            out[(size_t)t * H * B + (size_t)(r0 + orow) * B + ob] = y;
            m_prev = Mb;
        }
    }

    // ---- final fold: block b (<16): final[b] = log(sum_h softmax(gamma)_h *
    //      E_{S-1}[h,b]) + g_shift[(S-2)&1][b]
    if (blk < 16) {
        if (tid < NBLK) {
            volatile unsigned* f = &g_flag[tid];
            const unsigned bs = base + (unsigned)S;
            while (*f < bs) {}
        }
        __syncthreads();

        float gv[4];
        #pragma unroll
        for (int i = 0; i < 4; i++) gv[i] = __ldg(&gamma[tid + i * NTHR]);
        float gm = fmaxf(fmaxf(gv[0], gv[1]), fmaxf(gv[2], gv[3]));
        #pragma unroll
        for (int o = 16; o > 0; o >>= 1)
            gm = fmaxf(gm, __shfl_xor_sync(0xffffffffu, gm, o));
        if (lane == 0) s_misc[64 + w] = gm;
        __syncthreads();
        float gmax = s_misc[64];
        #pragma unroll
        for (int c = 1; c < 16; c++) gmax = fmaxf(gmax, s_misc[64 + c]);

        const float* El = g_E[(S - 1) & 1];
        float qs = 0.f, sm = 0.f;
        #pragma unroll
        for (int i = 0; i < 4; i++) {
            int h = tid + i * NTHR;
            float q = __expf(gv[i] - gmax);
            qs += q;
            sm += q * __ldcg(El + (size_t)h * B + blk);
        }
        #pragma unroll
        for (int o = 16; o > 0; o >>= 1) {
            qs += __shfl_xor_sync(0xffffffffu, qs, o);
            sm += __shfl_xor_sync(0xffffffffu, sm, o);
        }
        if (lane == 0) { s_misc[w] = qs; s_misc[32 + w] = sm; }
        __syncthreads();

        if (tid == 0) {
            float gsum = 0.f, tot = 0.f;
            #pragma unroll
            for (int c = 0; c < 16; c++) { gsum += s_misc[c]; tot += s_misc[32 + c]; }
            float shift = __ldcg(&g_shift[(S - 2) & 1][blk]);
            out[(size_t)S * H * B + blk] = __logf(tot) - __logf(gsum) + shift;
        }
    }
}

// ---------------------------------------------------------------------------
extern "C" void kernel_launch(void* const* d_in, const int* in_sizes, int n_in,
                              void* d_out, int out_size) {
    const int* ids = (const int*)d_in[0];        // (B, S) int32
    const float* alpha = (const float*)d_in[1];  // (H, H)
    const float* beta = (const float*)d_in[2];   // (H, V)
    const float* gamma = (const float*)d_in[3];  // (H,)
    float* out = (float*)d_out;                  // ys (S,H,B) then final (B,)

    const int smem_main = (256 * PPAD + 128) * (int)sizeof(float);
    cudaFuncSetAttribute(hmm_persist, cudaFuncAttributeMaxDynamicSharedMemorySize,
                         smem_main);

    hmm_persist<<<NBLK, NTHR, smem_main>>>(ids, alpha, beta, gamma, out);
}